// round 1
// baseline (speedup 1.0000x reference)
#include <cuda_runtime.h>

#define TDIM 512
#define NREC 256
#define NIN 10
#define NOUT 3
#define BATCH 1024
#define ROWS 8
#define NB (BATCH/ROWS)   // 128 blocks
#define NT 128            // threads per block

typedef unsigned long long u64;

__device__ float g_WT[NREC*NREC];   // WT[j][n] = W_rec[n][j]
__device__ float g_l2p[NB];

__device__ __forceinline__ u64 pk(float a, float b){
    u64 r; asm("mov.b64 %0,{%1,%2};":"=l"(r):"f"(a),"f"(b)); return r;
}
__device__ __forceinline__ u64 fm2(u64 a, u64 b, u64 c){
    u64 d; asm("fma.rn.f32x2 %0,%1,%2,%3;":"=l"(d):"l"(a),"l"(b),"l"(c)); return d;
}
__device__ __forceinline__ float2 up(u64 v){
    float2 f; asm("mov.b64 {%0,%1},%2;":"=f"(f.x),"=f"(f.y):"l"(v)); return f;
}

// Tiled transpose: g_WT[j*256+n] = W[n*256+j], coalesced both ways.
__global__ void tr_kernel(const float* __restrict__ W){
    __shared__ float tile[32][33];
    int bx = blockIdx.x & 7;        // j tile
    int by = blockIdx.x >> 3;       // n tile
    int lx = threadIdx.x & 31, ly = threadIdx.x >> 5;   // 32 x 8
    #pragma unroll
    for (int q = 0; q < 32; q += 8)
        tile[ly+q][lx] = W[(by*32 + ly + q)*NREC + bx*32 + lx];
    __syncthreads();
    #pragma unroll
    for (int q = 0; q < 32; q += 8)
        g_WT[(bx*32 + ly + q)*NREC + by*32 + lx] = tile[lx][ly+q];
}

__global__ __launch_bounds__(NT, 1)
void rnn_kernel(const float* __restrict__ x,
                const float* __restrict__ noise,
                const float* __restrict__ W_in,
                const float* __restrict__ W_out,
                const float* __restrict__ b_out,
                const float* __restrict__ bias,
                float* __restrict__ out)
{
    extern __shared__ float sm[];
    float* Wlo = sm;                        // [256][128]  cols 0..127, 128 KB
    float* rT  = Wlo + NREC*NT;             // [2][256][8] double-buffered r^T
    float* WoS = rT + 2*NREC*ROWS;          // [3][256]
    float* xb  = WoS + NOUT*NREC;           // [2][8][12]

    const int tid = threadIdx.x;
    const int b0  = blockIdx.x * ROWS;
    const int c0  = tid;
    const int c1  = tid + NT;

    // ---- init ----
    for (int idx = tid; idx < NREC*NT; idx += NT){
        int j = idx >> 7, n = idx & 127;
        Wlo[idx] = g_WT[j*NREC + n];
    }
    for (int idx = tid; idx < 2*NREC*ROWS; idx += NT) rT[idx] = 0.f;
    for (int idx = tid; idx < NOUT*NREC; idx += NT) WoS[idx] = W_out[idx];
    if (tid < ROWS*NIN){
        int i = tid/NIN, k = tid%NIN;
        xb[i*12 + k] = x[(size_t)(b0+i)*TDIM*NIN + k];   // t = 0 into buf 0
    }

    float win0[NIN], win1[NIN];
    #pragma unroll
    for (int k = 0; k < NIN; k++){
        win0[k] = W_in[c0*NIN + k];
        win1[k] = W_in[c1*NIN + k];
    }
    const float bs0 = bias[c0], bs1 = bias[c1];
    const float bo0 = b_out[0], bo1 = b_out[1], bo2 = b_out[2];

    float r0[ROWS], r1[ROWS];
    #pragma unroll
    for (int i = 0; i < ROWS; i++){ r0[i] = 0.f; r1[i] = 0.f; }

    // prefetch noise for t=0
    float nz0[ROWS], nz1[ROWS];
    #pragma unroll
    for (int i = 0; i < ROWS; i++){
        size_t nb = ((size_t)(b0+i)*TDIM)*NREC;
        nz0[i] = noise[nb + c0];
        nz1[i] = noise[nb + c1];
    }
    double l2d = 0.0;
    __syncthreads();

    const int wid  = tid >> 5, lane = tid & 31;
    const int row0 = 2*wid, row1 = 2*wid + 1;

    for (int t = 0; t < TDIM; t++){
        const int cur = t & 1, nxt = cur ^ 1;
        const float* rTc = rT + cur*NREC*ROWS;
        float*       rTn = rT + nxt*NREC*ROWS;
        const float* xbc = xb + cur*96;
        float*       xbn = xb + nxt*96;

        // u = bias + noise + x @ W_in^T
        float u0[ROWS], u1[ROWS];
        #pragma unroll
        for (int i = 0; i < ROWS; i++){ u0[i] = bs0 + nz0[i]; u1[i] = bs1 + nz1[i]; }
        #pragma unroll
        for (int i = 0; i < ROWS; i++){
            #pragma unroll
            for (int k = 0; k < NIN; k++){
                float xv = xbc[i*12 + k];
                u0[i] = fmaf(xv, win0[k], u0[i]);
                u1[i] = fmaf(xv, win1[k], u1[i]);
            }
        }

        // prefetch next-step noise (DRAM latency hidden under the GEMM)
        {
            int tn = (t+1 < TDIM) ? t+1 : t;
            #pragma unroll
            for (int i = 0; i < ROWS; i++){
                size_t nb = ((size_t)(b0+i)*TDIM + tn)*NREC;
                nz0[i] = noise[nb + c0];
                nz1[i] = noise[nb + c1];
            }
        }

        // accumulators (row pairs packed into f32x2)
        u64 a0[4], a1[4];
        #pragma unroll
        for (int p = 0; p < 4; p++){
            a0[p] = pk(u0[2*p], u0[2*p+1]);
            a1[p] = pk(u1[2*p], u1[2*p+1]);
        }

        // v += r @ W_rec^T  : col c0 from SMEM weights, col c1 streamed from L2
        const ulonglong2* rT2 = (const ulonglong2*)rTc;
        #pragma unroll 8
        for (int j = 0; j < NREC; j++){
            float w0 = Wlo[(j << 7) + tid];
            float w1 = __ldg(&g_WT[j*NREC + c1]);
            ulonglong2 qa = rT2[2*j];
            ulonglong2 qb = rT2[2*j + 1];
            u64 w00 = pk(w0, w0), w11 = pk(w1, w1);
            a0[0] = fm2(qa.x, w00, a0[0]);
            a0[1] = fm2(qa.y, w00, a0[1]);
            a0[2] = fm2(qb.x, w00, a0[2]);
            a0[3] = fm2(qb.y, w00, a0[3]);
            a1[0] = fm2(qa.x, w11, a1[0]);
            a1[1] = fm2(qa.y, w11, a1[1]);
            a1[2] = fm2(qb.x, w11, a1[2]);
            a1[3] = fm2(qb.y, w11, a1[3]);
        }

        // r_new = 0.8 r + 0.2 relu(v)
        #pragma unroll
        for (int p = 0; p < 4; p++){
            float2 v0 = up(a0[p]);
            float2 v1 = up(a1[p]);
            int i0 = 2*p, i1 = 2*p + 1;
            r0[i0] = 0.8f*r0[i0] + 0.2f*fmaxf(v0.x, 0.f);
            r0[i1] = 0.8f*r0[i1] + 0.2f*fmaxf(v0.y, 0.f);
            r1[i0] = 0.8f*r1[i0] + 0.2f*fmaxf(v1.x, 0.f);
            r1[i1] = 0.8f*r1[i1] + 0.2f*fmaxf(v1.y, 0.f);
        }

        float ssum = 0.f;
        #pragma unroll
        for (int i = 0; i < ROWS; i++){
            rTn[c0*ROWS + i] = r0[i];
            rTn[c1*ROWS + i] = r1[i];
            ssum = fmaf(r0[i], r0[i], ssum);
            ssum = fmaf(r1[i], r1[i], ssum);
        }
        l2d += (double)ssum;

        // prefetch next x tile into the other buffer
        if (tid < ROWS*NIN){
            int i = tid/NIN, k = tid%NIN;
            int tn = (t+1 < TDIM) ? t+1 : t;
            xbn[i*12 + k] = x[((size_t)(b0+i)*TDIM + tn)*NIN + k];
        }

        __syncthreads();   // rTn complete for everyone

        // z = r_new @ W_out^T + b_out  (warp w -> rows 2w, 2w+1)
        {
            float z00=0.f, z01=0.f, z02=0.f, z10=0.f, z11=0.f, z12=0.f;
            #pragma unroll
            for (int q = 0; q < NREC/32; q++){
                int jj = lane + 32*q;
                float ra = rTn[jj*ROWS + row0];
                float rb = rTn[jj*ROWS + row1];
                float wo0 = WoS[jj], wo1 = WoS[NREC + jj], wo2 = WoS[2*NREC + jj];
                z00 = fmaf(ra, wo0, z00); z01 = fmaf(ra, wo1, z01); z02 = fmaf(ra, wo2, z02);
                z10 = fmaf(rb, wo0, z10); z11 = fmaf(rb, wo1, z11); z12 = fmaf(rb, wo2, z12);
            }
            #pragma unroll
            for (int off = 16; off; off >>= 1){
                z00 += __shfl_down_sync(~0u, z00, off);
                z01 += __shfl_down_sync(~0u, z01, off);
                z02 += __shfl_down_sync(~0u, z02, off);
                z10 += __shfl_down_sync(~0u, z10, off);
                z11 += __shfl_down_sync(~0u, z11, off);
                z12 += __shfl_down_sync(~0u, z12, off);
            }
            if (lane == 0){
                size_t ob = ((size_t)(b0 + row0)*TDIM + t)*NOUT;
                out[ob+0] = z00 + bo0; out[ob+1] = z01 + bo1; out[ob+2] = z02 + bo2;
                ob = ((size_t)(b0 + row1)*TDIM + t)*NOUT;
                out[ob+0] = z10 + bo0; out[ob+1] = z11 + bo1; out[ob+2] = z12 + bo2;
            }
        }
    }

    // block-level deterministic l2 reduction
    __syncthreads();
    double* dd = (double*)rT;
    dd[tid] = l2d;
    __syncthreads();
    if (tid == 0){
        double s = 0.0;
        for (int i = 0; i < NT; i++) s += dd[i];
        g_l2p[blockIdx.x] = (float)s;
    }
}

__global__ void l2_final(float* __restrict__ out, int out_size){
    __shared__ double s[NB];
    s[threadIdx.x] = (double)g_l2p[threadIdx.x];
    __syncthreads();
    if (threadIdx.x == 0){
        double tot = 0.0;
        for (int i = 0; i < NB; i++) tot += s[i];
        out[out_size - 1] = (float)(tot / ((double)TDIM * BATCH * NREC));
    }
}

extern "C" void kernel_launch(void* const* d_in, const int* in_sizes, int n_in,
                              void* d_out, int out_size)
{
    const float* x     = (const float*)d_in[0];
    const float* noise = (const float*)d_in[1];
    const float* W_in  = (const float*)d_in[2];
    const float* W_rec = (const float*)d_in[3];
    const float* W_out = (const float*)d_in[4];
    const float* b_out = (const float*)d_in[5];
    const float* bias  = (const float*)d_in[6];
    float* out = (float*)d_out;

    size_t smem = (size_t)(NREC*NT + 2*NREC*ROWS + NOUT*NREC + 2*96) * sizeof(float);
    cudaFuncSetAttribute(rnn_kernel, cudaFuncAttributeMaxDynamicSharedMemorySize, (int)smem);

    tr_kernel<<<64, 256>>>(W_rec);
    rnn_kernel<<<NB, NT, smem>>>(x, noise, W_in, W_out, b_out, bias, out);
    l2_final<<<1, NB>>>(out, out_size);
}

// round 2
// speedup vs baseline: 1.8495x; 1.8495x over previous
#include <cuda_runtime.h>

#define TDIM 512
#define NREC 256
#define NIN 10
#define NOUT 3
#define BATCH 1024
#define ROWS 8
#define NB (BATCH/ROWS)     // 128 blocks
#define NT 128              // 4 warps, 1 per SMSP
#define JS 128              // j rows cached in SMEM
#define WPAD 132            // padded W row (floats): conflict-free LDS.128
#define NSTREAM ((NREC-JS)/4)   // 32 blocks of 4 j streamed from L2

typedef unsigned long long u64;

__device__ ulonglong2 g_Wst[NSTREAM * NREC];   // [ (j-128)/4 ][ c ] : W^T 4-j packs, 128 KB
__device__ float g_l2p[NB];
__device__ unsigned int g_ctr;

static __device__ __forceinline__ u64 pk(float a, float b){
    u64 r; asm("mov.b64 %0,{%1,%2};":"=l"(r):"f"(a),"f"(b)); return r;
}
static __device__ __forceinline__ u64 fm2(u64 a, u64 b, u64 c){
    u64 d; asm("fma.rn.f32x2 %0,%1,%2,%3;":"=l"(d):"l"(a),"l"(b),"l"(c)); return d;
}
static __device__ __forceinline__ float2 up(u64 v){
    float2 f; asm("mov.b64 {%0,%1},%2;":"=f"(f.x),"=f"(f.y):"l"(v)); return f;
}

// Build the streamed-weight table: g_Wst[k][c] = W_rec[c][128+4k .. 128+4k+3]
// (reading W_rec rows as float4 pairs; no transpose math needed)
__global__ void prep_kernel(const float* __restrict__ W){
    int c = threadIdx.x;   // 256 threads
    const ulonglong2* row = (const ulonglong2*)(W + c * NREC);
    #pragma unroll
    for (int k = 0; k < NSTREAM; k++)
        g_Wst[k * NREC + c] = row[JS/4 + k];
}

__global__ __launch_bounds__(NT, 1)
void rnn_kernel(const float* __restrict__ x,
                const float* __restrict__ noise,
                const float* __restrict__ W_in,
                const float* __restrict__ W_rec,
                const float* __restrict__ W_out,
                const float* __restrict__ b_out,
                const float* __restrict__ bias,
                float* __restrict__ out, int out_size)
{
    extern __shared__ float sm[];
    float* Wsm = sm;                         // [256][WPAD]  (j < 128), 132 KB
    float* rT  = Wsm + NREC * WPAD;          // [2][ROWS][NREC] double-buffered, r[row][j]
    float* WoS = rT + 2 * ROWS * NREC;       // [3][256]
    float* xb  = WoS + NOUT * NREC;          // [2][ROWS][12]

    const int tid = threadIdx.x;
    const int b0  = blockIdx.x * ROWS;
    const int c0  = tid;
    const int c1  = tid + NT;

    // ---- init SMEM ----
    for (int idx = tid; idx < NREC * JS; idx += NT){
        int c = idx >> 7, j = idx & (JS - 1);
        Wsm[c * WPAD + j] = W_rec[c * NREC + j];
    }
    for (int idx = tid; idx < 2 * ROWS * NREC; idx += NT) rT[idx] = 0.f;
    for (int idx = tid; idx < NOUT * NREC; idx += NT) WoS[idx] = W_out[idx];
    if (tid < ROWS * NIN){
        int i = tid / NIN, k = tid % NIN;
        xb[i * 12 + k] = x[(size_t)(b0 + i) * TDIM * NIN + k];   // t=0 into buf 0
    }

    float win0[NIN], win1[NIN];
    #pragma unroll
    for (int k = 0; k < NIN; k++){
        win0[k] = W_in[c0 * NIN + k];
        win1[k] = W_in[c1 * NIN + k];
    }
    const float bs0 = bias[c0], bs1 = bias[c1];
    const float bo0 = b_out[0], bo1 = b_out[1], bo2 = b_out[2];

    float r0[ROWS], r1[ROWS];
    #pragma unroll
    for (int i = 0; i < ROWS; i++){ r0[i] = 0.f; r1[i] = 0.f; }

    float nz0[ROWS], nz1[ROWS];
    #pragma unroll
    for (int i = 0; i < ROWS; i++){
        size_t nb = (size_t)(b0 + i) * TDIM * NREC;
        nz0[i] = noise[nb + c0];
        nz1[i] = noise[nb + c1];
    }
    double l2d = 0.0;
    __syncthreads();

    const int wid = tid >> 5, lane = tid & 31;
    const int row0 = 2 * wid, row1 = 2 * wid + 1;

    const ulonglong2* __restrict__ wA0 = (const ulonglong2*)(Wsm + c0 * WPAD);
    const ulonglong2* __restrict__ wA1 = (const ulonglong2*)(Wsm + c1 * WPAD);
    const ulonglong2* __restrict__ gw  = g_Wst;

    for (int t = 0; t < TDIM; t++){
        const int cur = t & 1, nxt = cur ^ 1;
        const float* rTc = rT + cur * ROWS * NREC;
        float*       rTn = rT + nxt * ROWS * NREC;
        const float* xbc = xb + cur * 96;
        float*       xbn = xb + nxt * 96;

        // u = bias + noise + x @ W_in^T   (scalar; ~240 inst, ~5% of step)
        float u0[ROWS], u1[ROWS];
        #pragma unroll
        for (int i = 0; i < ROWS; i++){ u0[i] = bs0 + nz0[i]; u1[i] = bs1 + nz1[i]; }
        #pragma unroll
        for (int i = 0; i < ROWS; i++){
            #pragma unroll
            for (int k = 0; k < NIN; k++){
                float xv = xbc[i * 12 + k];
                u0[i] = fmaf(xv, win0[k], u0[i]);
                u1[i] = fmaf(xv, win1[k], u1[i]);
            }
        }

        // prefetch next-step noise into registers (hidden under GEMM)
        {
            int tn = (t + 1 < TDIM) ? t + 1 : t;
            #pragma unroll
            for (int i = 0; i < ROWS; i++){
                size_t nb = ((size_t)(b0 + i) * TDIM + tn) * NREC;
                nz0[i] = noise[nb + c0];
                nz1[i] = noise[nb + c1];
            }
        }

        // accumulators: lane.x sums even-j products (+u), lane.y odd-j
        u64 a0[ROWS], a1[ROWS];
        #pragma unroll
        for (int i = 0; i < ROWS; i++){
            a0[i] = pk(u0[i], 0.f);
            a1[i] = pk(u1[i], 0.f);
        }

        const ulonglong2* __restrict__ rr = (const ulonglong2*)rTc;  // [ROWS][64]

        // ---- phase A: j in [0,128), weights from SMEM ----
        #pragma unroll 8
        for (int jb = 0; jb < JS/4; jb++){
            ulonglong2 w0 = wA0[jb];
            ulonglong2 w1 = wA1[jb];
            #pragma unroll
            for (int i = 0; i < ROWS; i++){
                ulonglong2 rv = rr[i * 64 + jb];
                a0[i] = fm2(rv.x, w0.x, a0[i]);
                a0[i] = fm2(rv.y, w0.y, a0[i]);
                a1[i] = fm2(rv.x, w1.x, a1[i]);
                a1[i] = fm2(rv.y, w1.y, a1[i]);
            }
        }
        // ---- phase B: j in [128,256), weights streamed from L2 (LDG.128) ----
        #pragma unroll 8
        for (int kb = 0; kb < NSTREAM; kb++){
            ulonglong2 w0 = gw[kb * NREC + c0];
            ulonglong2 w1 = gw[kb * NREC + c1];
            #pragma unroll
            for (int i = 0; i < ROWS; i++){
                ulonglong2 rv = rr[i * 64 + JS/4 + kb];
                a0[i] = fm2(rv.x, w0.x, a0[i]);
                a0[i] = fm2(rv.y, w0.y, a0[i]);
                a1[i] = fm2(rv.x, w1.x, a1[i]);
                a1[i] = fm2(rv.y, w1.y, a1[i]);
            }
        }

        // r_new = 0.8 r + 0.2 relu(v);  v = lane.x + lane.y
        float ssum = 0.f;
        #pragma unroll
        for (int i = 0; i < ROWS; i++){
            float2 v0 = up(a0[i]);
            float2 v1 = up(a1[i]);
            float vv0 = v0.x + v0.y;
            float vv1 = v1.x + v1.y;
            r0[i] = 0.8f * r0[i] + 0.2f * fmaxf(vv0, 0.f);
            r1[i] = 0.8f * r1[i] + 0.2f * fmaxf(vv1, 0.f);
            rTn[i * NREC + c0] = r0[i];
            rTn[i * NREC + c1] = r1[i];
            ssum = fmaf(r0[i], r0[i], ssum);
            ssum = fmaf(r1[i], r1[i], ssum);
        }
        l2d += (double)ssum;

        // prefetch next x tile
        if (tid < ROWS * NIN){
            int i = tid / NIN, k = tid % NIN;
            int tn = (t + 1 < TDIM) ? t + 1 : t;
            xbn[i * 12 + k] = x[((size_t)(b0 + i) * TDIM + tn) * NIN + k];
        }

        __syncthreads();   // rTn complete

        // z = r_new @ W_out^T + b_out ; warp w -> rows 2w, 2w+1
        {
            float z00=0.f, z01=0.f, z02=0.f, z10=0.f, z11=0.f, z12=0.f;
            #pragma unroll
            for (int q = 0; q < NREC/32; q++){
                int jj = lane + 32 * q;
                float ra = rTn[row0 * NREC + jj];
                float rb = rTn[row1 * NREC + jj];
                float wo0 = WoS[jj], wo1 = WoS[NREC + jj], wo2 = WoS[2*NREC + jj];
                z00 = fmaf(ra, wo0, z00); z01 = fmaf(ra, wo1, z01); z02 = fmaf(ra, wo2, z02);
                z10 = fmaf(rb, wo0, z10); z11 = fmaf(rb, wo1, z11); z12 = fmaf(rb, wo2, z12);
            }
            #pragma unroll
            for (int off = 16; off; off >>= 1){
                z00 += __shfl_down_sync(~0u, z00, off);
                z01 += __shfl_down_sync(~0u, z01, off);
                z02 += __shfl_down_sync(~0u, z02, off);
                z10 += __shfl_down_sync(~0u, z10, off);
                z11 += __shfl_down_sync(~0u, z11, off);
                z12 += __shfl_down_sync(~0u, z12, off);
            }
            if (lane == 0){
                size_t ob = ((size_t)(b0 + row0) * TDIM + t) * NOUT;
                out[ob+0] = z00 + bo0; out[ob+1] = z01 + bo1; out[ob+2] = z02 + bo2;
                ob = ((size_t)(b0 + row1) * TDIM + t) * NOUT;
                out[ob+0] = z10 + bo0; out[ob+1] = z11 + bo1; out[ob+2] = z12 + bo2;
            }
        }
    }

    // ---- deterministic l2 reduction, last-block finalization ----
    __syncthreads();
    double* dd = (double*)sm;
    dd[tid] = l2d;
    __syncthreads();
    if (tid == 0){
        double s = 0.0;
        #pragma unroll 8
        for (int i = 0; i < NT; i++) s += dd[i];
        g_l2p[blockIdx.x] = (float)s;
        __threadfence();
        unsigned int old = atomicInc(&g_ctr, NB - 1);
        if (old == NB - 1){
            __threadfence();
            double tot = 0.0;
            for (int i = 0; i < NB; i++) tot += (double)g_l2p[i];
            out[out_size - 1] = (float)(tot / ((double)TDIM * BATCH * NREC));
        }
    }
}

extern "C" void kernel_launch(void* const* d_in, const int* in_sizes, int n_in,
                              void* d_out, int out_size)
{
    const float* x     = (const float*)d_in[0];
    const float* noise = (const float*)d_in[1];
    const float* W_in  = (const float*)d_in[2];
    const float* W_rec = (const float*)d_in[3];
    const float* W_out = (const float*)d_in[4];
    const float* b_out = (const float*)d_in[5];
    const float* bias  = (const float*)d_in[6];
    float* out = (float*)d_out;

    size_t smem = (size_t)(NREC*WPAD + 2*ROWS*NREC + NOUT*NREC + 2*96) * sizeof(float);
    cudaFuncSetAttribute(rnn_kernel, cudaFuncAttributeMaxDynamicSharedMemorySize, (int)smem);

    prep_kernel<<<1, 256>>>(W_rec);
    rnn_kernel<<<NB, NT, smem>>>(x, noise, W_in, W_rec, W_out, b_out, bias, out, out_size);
}

// round 3
// speedup vs baseline: 1.8542x; 1.0025x over previous
#include <cuda_runtime.h>

#define TDIM 512
#define NREC 256
#define NIN 10
#define NOUT 3
#define BATCH 1024
#define ROWS 8
#define NB (BATCH/ROWS)     // 128 blocks
#define NT 128              // 4 warps, 1 per SMSP
#define JS 128              // j rows cached in SMEM
#define WPAD 132            // padded W row (floats): conflict-free LDS.128
#define NSTREAM ((NREC-JS)/4)   // 32 blocks of 4 j streamed from L2

typedef unsigned long long u64;

__device__ ulonglong2 g_Wst[NSTREAM * NREC];   // [ (j-128)/4 ][ c ] : W^T 4-j packs, 128 KB
__device__ float g_l2p[NB];
__device__ unsigned int g_ctr;

static __device__ __forceinline__ u64 pk(float a, float b){
    u64 r; asm("mov.b64 %0,{%1,%2};":"=l"(r):"f"(a),"f"(b)); return r;
}
static __device__ __forceinline__ u64 fm2(u64 a, u64 b, u64 c){
    u64 d; asm("fma.rn.f32x2 %0,%1,%2,%3;":"=l"(d):"l"(a),"l"(b),"l"(c)); return d;
}
static __device__ __forceinline__ float2 up(u64 v){
    float2 f; asm("mov.b64 {%0,%1},%2;":"=f"(f.x),"=f"(f.y):"l"(v)); return f;
}

// Build the streamed-weight table: g_Wst[k][c] = W_rec[c][128+4k .. 128+4k+3]
// (reading W_rec rows as float4 pairs; no transpose math needed)
__global__ void prep_kernel(const float* __restrict__ W){
    int c = threadIdx.x;   // 256 threads
    const ulonglong2* row = (const ulonglong2*)(W + c * NREC);
    #pragma unroll
    for (int k = 0; k < NSTREAM; k++)
        g_Wst[k * NREC + c] = row[JS/4 + k];
}

__global__ __launch_bounds__(NT, 1)
void rnn_kernel(const float* __restrict__ x,
                const float* __restrict__ noise,
                const float* __restrict__ W_in,
                const float* __restrict__ W_rec,
                const float* __restrict__ W_out,
                const float* __restrict__ b_out,
                const float* __restrict__ bias,
                float* __restrict__ out, int out_size)
{
    extern __shared__ float sm[];
    float* Wsm = sm;                         // [256][WPAD]  (j < 128), 132 KB
    float* rT  = Wsm + NREC * WPAD;          // [2][ROWS][NREC] double-buffered, r[row][j]
    float* WoS = rT + 2 * ROWS * NREC;       // [3][256]
    float* xb  = WoS + NOUT * NREC;          // [2][ROWS][12]

    const int tid = threadIdx.x;
    const int b0  = blockIdx.x * ROWS;
    const int c0  = tid;
    const int c1  = tid + NT;

    // ---- init SMEM ----
    for (int idx = tid; idx < NREC * JS; idx += NT){
        int c = idx >> 7, j = idx & (JS - 1);
        Wsm[c * WPAD + j] = W_rec[c * NREC + j];
    }
    for (int idx = tid; idx < 2 * ROWS * NREC; idx += NT) rT[idx] = 0.f;
    for (int idx = tid; idx < NOUT * NREC; idx += NT) WoS[idx] = W_out[idx];
    if (tid < ROWS * NIN){
        int i = tid / NIN, k = tid % NIN;
        xb[i * 12 + k] = x[(size_t)(b0 + i) * TDIM * NIN + k];   // t=0 into buf 0
    }

    float win0[NIN], win1[NIN];
    #pragma unroll
    for (int k = 0; k < NIN; k++){
        win0[k] = W_in[c0 * NIN + k];
        win1[k] = W_in[c1 * NIN + k];
    }
    const float bs0 = bias[c0], bs1 = bias[c1];
    const float bo0 = b_out[0], bo1 = b_out[1], bo2 = b_out[2];

    float r0[ROWS], r1[ROWS];
    #pragma unroll
    for (int i = 0; i < ROWS; i++){ r0[i] = 0.f; r1[i] = 0.f; }

    float nz0[ROWS], nz1[ROWS];
    #pragma unroll
    for (int i = 0; i < ROWS; i++){
        size_t nb = (size_t)(b0 + i) * TDIM * NREC;
        nz0[i] = noise[nb + c0];
        nz1[i] = noise[nb + c1];
    }
    double l2d = 0.0;
    __syncthreads();

    const int wid = tid >> 5, lane = tid & 31;
    const int row0 = 2 * wid, row1 = 2 * wid + 1;

    const ulonglong2* __restrict__ wA0 = (const ulonglong2*)(Wsm + c0 * WPAD);
    const ulonglong2* __restrict__ wA1 = (const ulonglong2*)(Wsm + c1 * WPAD);
    const ulonglong2* __restrict__ gw  = g_Wst;

    for (int t = 0; t < TDIM; t++){
        const int cur = t & 1, nxt = cur ^ 1;
        const float* rTc = rT + cur * ROWS * NREC;
        float*       rTn = rT + nxt * ROWS * NREC;
        const float* xbc = xb + cur * 96;
        float*       xbn = xb + nxt * 96;

        // u = bias + noise + x @ W_in^T   (scalar; ~240 inst, ~5% of step)
        float u0[ROWS], u1[ROWS];
        #pragma unroll
        for (int i = 0; i < ROWS; i++){ u0[i] = bs0 + nz0[i]; u1[i] = bs1 + nz1[i]; }
        #pragma unroll
        for (int i = 0; i < ROWS; i++){
            #pragma unroll
            for (int k = 0; k < NIN; k++){
                float xv = xbc[i * 12 + k];
                u0[i] = fmaf(xv, win0[k], u0[i]);
                u1[i] = fmaf(xv, win1[k], u1[i]);
            }
        }

        // prefetch next-step noise into registers (hidden under GEMM)
        {
            int tn = (t + 1 < TDIM) ? t + 1 : t;
            #pragma unroll
            for (int i = 0; i < ROWS; i++){
                size_t nb = ((size_t)(b0 + i) * TDIM + tn) * NREC;
                nz0[i] = noise[nb + c0];
                nz1[i] = noise[nb + c1];
            }
        }

        // accumulators: lane.x sums even-j products (+u), lane.y odd-j
        u64 a0[ROWS], a1[ROWS];
        #pragma unroll
        for (int i = 0; i < ROWS; i++){
            a0[i] = pk(u0[i], 0.f);
            a1[i] = pk(u1[i], 0.f);
        }

        const ulonglong2* __restrict__ rr = (const ulonglong2*)rTc;  // [ROWS][64]

        // ---- phase A: j in [0,128), weights from SMEM ----
        #pragma unroll 8
        for (int jb = 0; jb < JS/4; jb++){
            ulonglong2 w0 = wA0[jb];
            ulonglong2 w1 = wA1[jb];
            #pragma unroll
            for (int i = 0; i < ROWS; i++){
                ulonglong2 rv = rr[i * 64 + jb];
                a0[i] = fm2(rv.x, w0.x, a0[i]);
                a0[i] = fm2(rv.y, w0.y, a0[i]);
                a1[i] = fm2(rv.x, w1.x, a1[i]);
                a1[i] = fm2(rv.y, w1.y, a1[i]);
            }
        }
        // ---- phase B: j in [128,256), weights streamed from L2 (LDG.128) ----
        #pragma unroll 8
        for (int kb = 0; kb < NSTREAM; kb++){
            ulonglong2 w0 = gw[kb * NREC + c0];
            ulonglong2 w1 = gw[kb * NREC + c1];
            #pragma unroll
            for (int i = 0; i < ROWS; i++){
                ulonglong2 rv = rr[i * 64 + JS/4 + kb];
                a0[i] = fm2(rv.x, w0.x, a0[i]);
                a0[i] = fm2(rv.y, w0.y, a0[i]);
                a1[i] = fm2(rv.x, w1.x, a1[i]);
                a1[i] = fm2(rv.y, w1.y, a1[i]);
            }
        }

        // r_new = 0.8 r + 0.2 relu(v);  v = lane.x + lane.y
        float ssum = 0.f;
        #pragma unroll
        for (int i = 0; i < ROWS; i++){
            float2 v0 = up(a0[i]);
            float2 v1 = up(a1[i]);
            float vv0 = v0.x + v0.y;
            float vv1 = v1.x + v1.y;
            r0[i] = 0.8f * r0[i] + 0.2f * fmaxf(vv0, 0.f);
            r1[i] = 0.8f * r1[i] + 0.2f * fmaxf(vv1, 0.f);
            rTn[i * NREC + c0] = r0[i];
            rTn[i * NREC + c1] = r1[i];
            ssum = fmaf(r0[i], r0[i], ssum);
            ssum = fmaf(r1[i], r1[i], ssum);
        }
        l2d += (double)ssum;

        // prefetch next x tile
        if (tid < ROWS * NIN){
            int i = tid / NIN, k = tid % NIN;
            int tn = (t + 1 < TDIM) ? t + 1 : t;
            xbn[i * 12 + k] = x[((size_t)(b0 + i) * TDIM + tn) * NIN + k];
        }

        __syncthreads();   // rTn complete

        // z = r_new @ W_out^T + b_out ; warp w -> rows 2w, 2w+1
        {
            float z00=0.f, z01=0.f, z02=0.f, z10=0.f, z11=0.f, z12=0.f;
            #pragma unroll
            for (int q = 0; q < NREC/32; q++){
                int jj = lane + 32 * q;
                float ra = rTn[row0 * NREC + jj];
                float rb = rTn[row1 * NREC + jj];
                float wo0 = WoS[jj], wo1 = WoS[NREC + jj], wo2 = WoS[2*NREC + jj];
                z00 = fmaf(ra, wo0, z00); z01 = fmaf(ra, wo1, z01); z02 = fmaf(ra, wo2, z02);
                z10 = fmaf(rb, wo0, z10); z11 = fmaf(rb, wo1, z11); z12 = fmaf(rb, wo2, z12);
            }
            #pragma unroll
            for (int off = 16; off; off >>= 1){
                z00 += __shfl_down_sync(~0u, z00, off);
                z01 += __shfl_down_sync(~0u, z01, off);
                z02 += __shfl_down_sync(~0u, z02, off);
                z10 += __shfl_down_sync(~0u, z10, off);
                z11 += __shfl_down_sync(~0u, z11, off);
                z12 += __shfl_down_sync(~0u, z12, off);
            }
            if (lane == 0){
                size_t ob = ((size_t)(b0 + row0) * TDIM + t) * NOUT;
                out[ob+0] = z00 + bo0; out[ob+1] = z01 + bo1; out[ob+2] = z02 + bo2;
                ob = ((size_t)(b0 + row1) * TDIM + t) * NOUT;
                out[ob+0] = z10 + bo0; out[ob+1] = z11 + bo1; out[ob+2] = z12 + bo2;
            }
        }
    }

    // ---- deterministic l2 reduction, last-block finalization ----
    __syncthreads();
    double* dd = (double*)sm;
    dd[tid] = l2d;
    __syncthreads();
    if (tid == 0){
        double s = 0.0;
        #pragma unroll 8
        for (int i = 0; i < NT; i++) s += dd[i];
        g_l2p[blockIdx.x] = (float)s;
        __threadfence();
        unsigned int old = atomicInc(&g_ctr, NB - 1);
        if (old == NB - 1){
            __threadfence();
            double tot = 0.0;
            for (int i = 0; i < NB; i++) tot += (double)g_l2p[i];
            out[out_size - 1] = (float)(tot / ((double)TDIM * BATCH * NREC));
        }
    }
}

extern "C" void kernel_launch(void* const* d_in, const int* in_sizes, int n_in,
                              void* d_out, int out_size)
{
    const float* x     = (const float*)d_in[0];
    const float* noise = (const float*)d_in[1];
    const float* W_in  = (const float*)d_in[2];
    const float* W_rec = (const float*)d_in[3];
    const float* W_out = (const float*)d_in[4];
    const float* b_out = (const float*)d_in[5];
    const float* bias  = (const float*)d_in[6];
    float* out = (float*)d_out;

    size_t smem = (size_t)(NREC*WPAD + 2*ROWS*NREC + NOUT*NREC + 2*96) * sizeof(float);
    cudaFuncSetAttribute(rnn_kernel, cudaFuncAttributeMaxDynamicSharedMemorySize, (int)smem);

    prep_kernel<<<1, 256>>>(W_rec);
    rnn_kernel<<<NB, NT, smem>>>(x, noise, W_in, W_rec, W_out, b_out, bias, out, out_size);
}